// round 5
// baseline (speedup 1.0000x reference)
#include <cuda_runtime.h>

#define IN_CH   256
#define OUT_CH  256
#define NTASKS  64
#define WSIZE   (OUT_CH * IN_CH)
#define FULL_EMBED (WSIZE + OUT_CH)
#define BMAX    4096
#define MT      32                        // rows per X tile
#define NCOLS   64                        // output cols per CTA
#define THREADS 128
#define XSTRIDE 260                       // floats per X row (16B aligned, conflict-free)

#define WSM_F   (IN_CH * NCOLS)           // 16384 floats = 64KB, [k][c]
#define XSM_F   (MT * XSTRIDE)            // 8320 floats ~ 33.3KB, [r][k]
// smem: Wsm + Xsm + uint16 list[4096] + counter
#define SMEM_B  (((WSM_F + XSM_F) * 4) + (BMAX * 2) + 16)

__device__ __forceinline__ unsigned long long fma2(unsigned long long a,
                                                   unsigned long long b,
                                                   unsigned long long c) {
    unsigned long long d;
    asm("fma.rn.f32x2 %0, %1, %2, %3;" : "=l"(d) : "l"(a), "l"(b), "l"(c));
    return d;
}
__device__ __forceinline__ unsigned long long pack2(float x) {
    unsigned long long d;
    asm("mov.b64 %0, {%1, %1};" : "=l"(d) : "f"(x));
    return d;
}
__device__ __forceinline__ float2 unpack2(unsigned long long v) {
    float2 r;
    asm("mov.b64 {%0, %1}, %2;" : "=f"(r.x), "=f"(r.y) : "l"(v));
    return r;
}

// ================= main: CTA = (task, 64-col chunk), fused compaction ======
__global__ __launch_bounds__(THREADS, 2)
void affine_kernel(const float* __restrict__ inputs,
                   const int* __restrict__ task_ids,
                   const float* __restrict__ te,
                   float* __restrict__ out,
                   int B) {
    extern __shared__ float smem[];
    float*          Wsm  = smem;                       // [k][c]
    float*          Xsm  = smem + WSM_F;               // [r][k], stride XSTRIDE
    unsigned short* list = (unsigned short*)(Xsm + XSM_F);
    int*            s_n  = (int*)(list + BMAX);

    const int task    = blockIdx.y;
    const int colBase = blockIdx.x * NCOLS;
    const int tid     = threadIdx.x;
    const int lane    = tid & 31;
    const int warp    = tid >> 5;

    if (tid == 0) s_n[0] = 0;
    __syncthreads();

    // ---- fused compaction: this task's sample indices -> smem (uint16) ----
    for (int i = tid; i < B; i += THREADS) {
        if (task_ids[i] == task) {
            int p = atomicAdd(s_n, 1);
            list[p] = (unsigned short)i;
        }
    }

    // ---- stage W transposed to [k][c] (thread-per-column, 2 k-halves) ----
    const float* emb = te + (size_t)task * FULL_EMBED;
    {
        const int c  = tid & (NCOLS - 1);
        const int ks = (tid >> 6) * 128;
        const float4* wg = (const float4*)(emb + (size_t)(colBase + c) * IN_CH + ks);
        #pragma unroll
        for (int kv = 0; kv < 32; kv++) {
            float4 v = wg[kv];
            int k = ks + kv * 4;
            Wsm[(k + 0) * NCOLS + c] = v.x;
            Wsm[(k + 1) * NCOLS + c] = v.y;
            Wsm[(k + 2) * NCOLS + c] = v.z;
            Wsm[(k + 3) * NCOLS + c] = v.w;
        }
    }
    __syncthreads();

    const int n = s_n[0];
    if (n == 0) return;

    // ---- thread tile: 2 rows x 8 cols (two 4-col groups 32 apart) ----
    const int g  = tid & 7;                 // col group 0..7
    const int rg = tid >> 3;                // row group 0..15
    const int r0 = rg * 2;
    const int cA = g * 4;
    const int cB = 32 + g * 4;

    float biasA[4], biasB[4];
    #pragma unroll
    for (int j = 0; j < 4; j++) {
        biasA[j] = emb[WSIZE + colBase + cA + j];
        biasB[j] = emb[WSIZE + colBase + cB + j];
    }

    for (int m0 = 0; m0 < n; m0 += MT) {
        __syncthreads();                    // Xsm reusable

        // ---- stage X: warp-per-row, full-row coalesced (512B per row) ----
        #pragma unroll
        for (int rr = 0; rr < 8; rr++) {
            int r   = warp * 8 + rr;
            int row = m0 + r;
            float4* xrow = (float4*)(Xsm + r * XSTRIDE);
            if (row < n) {
                const float4* xg =
                    (const float4*)(inputs + (size_t)list[row] * IN_CH);
                float4 v0 = xg[lane];
                float4 v1 = xg[lane + 32];
                xrow[lane]      = v0;
                xrow[lane + 32] = v1;
            } else {
                xrow[lane]      = make_float4(0.f, 0.f, 0.f, 0.f);
                xrow[lane + 32] = make_float4(0.f, 0.f, 0.f, 0.f);
            }
        }
        __syncthreads();

        unsigned long long a00 = 0, a01 = 0, a02 = 0, a03 = 0;
        unsigned long long a10 = 0, a11 = 0, a12 = 0, a13 = 0;

        const float* x0p = Xsm + r0 * XSTRIDE;
        const float* x1p = x0p + XSTRIDE;
        const float* wp  = Wsm + cA;

        #pragma unroll 2
        for (int k4 = 0; k4 < IN_CH / 4; k4++) {
            float4 xv0 = *(const float4*)(x0p + k4 * 4);
            float4 xv1 = *(const float4*)(x1p + k4 * 4);
            #pragma unroll
            for (int kk = 0; kk < 4; kk++) {
                const float* wk = wp + (k4 * 4 + kk) * NCOLS;
                ulonglong2 wA = *(const ulonglong2*)wk;
                ulonglong2 wB = *(const ulonglong2*)(wk + 32);
                float x0 = (kk == 0) ? xv0.x : (kk == 1) ? xv0.y
                         : (kk == 2) ? xv0.z : xv0.w;
                float x1 = (kk == 0) ? xv1.x : (kk == 1) ? xv1.y
                         : (kk == 2) ? xv1.z : xv1.w;
                unsigned long long p0 = pack2(x0);
                unsigned long long p1 = pack2(x1);
                a00 = fma2(wA.x, p0, a00);
                a01 = fma2(wA.y, p0, a01);
                a02 = fma2(wB.x, p0, a02);
                a03 = fma2(wB.y, p0, a03);
                a10 = fma2(wA.x, p1, a10);
                a11 = fma2(wA.y, p1, a11);
                a12 = fma2(wB.x, p1, a12);
                a13 = fma2(wB.y, p1, a13);
            }
        }

        // ---- epilogue: 2 rows, two STG.128 each ----
        int row0 = m0 + r0;
        if (row0 < n) {
            float* orow = out + (size_t)list[row0] * OUT_CH + colBase;
            float2 vA0 = unpack2(a00), vA1 = unpack2(a01);
            float2 vB0 = unpack2(a02), vB1 = unpack2(a03);
            *(float4*)(orow + cA) = make_float4(vA0.x + biasA[0], vA0.y + biasA[1],
                                                vA1.x + biasA[2], vA1.y + biasA[3]);
            *(float4*)(orow + cB) = make_float4(vB0.x + biasB[0], vB0.y + biasB[1],
                                                vB1.x + biasB[2], vB1.y + biasB[3]);
        }
        if (row0 + 1 < n) {
            float* orow = out + (size_t)list[row0 + 1] * OUT_CH + colBase;
            float2 vA0 = unpack2(a10), vA1 = unpack2(a11);
            float2 vB0 = unpack2(a12), vB1 = unpack2(a13);
            *(float4*)(orow + cA) = make_float4(vA0.x + biasA[0], vA0.y + biasA[1],
                                                vA1.x + biasA[2], vA1.y + biasA[3]);
            *(float4*)(orow + cB) = make_float4(vB0.x + biasB[0], vB0.y + biasB[1],
                                                vB1.x + biasB[2], vB1.y + biasB[3]);
        }
    }
}

// ================= launch ==================================================
extern "C" void kernel_launch(void* const* d_in, const int* in_sizes, int n_in,
                              void* d_out, int out_size) {
    const float* inputs   = (const float*)d_in[0];
    const int*   task_ids = (const int*)d_in[1];   // JAX x64 disabled -> int32
    const float* te       = (const float*)d_in[2];
    float*       out      = (float*)d_out;
    int B = in_sizes[1];

    cudaFuncSetAttribute(affine_kernel,
                         cudaFuncAttributeMaxDynamicSharedMemorySize, SMEM_B);
    dim3 grid(OUT_CH / NCOLS, NTASKS, 1);   // (4, 64) = 256 CTAs, 2/SM
    affine_kernel<<<grid, THREADS, SMEM_B>>>(inputs, task_ids, te, out, B);
}

// round 7
// speedup vs baseline: 1.7967x; 1.7967x over previous
#include <cuda_runtime.h>
#include <cuda_bf16.h>
#include <cstdint>

#define IN_CH   256
#define OUT_CH  256
#define NTASKS  64
#define WSIZE   (OUT_CH * IN_CH)
#define FULL_EMBED (WSIZE + OUT_CH)
#define BMAX    4096
#define LIST_STRIDE 4096
#define NCOLS   128             // output cols per CTA
#define MT      32              // rows per M-tile
#define THREADS 256

// bf16 row stride: 264 elements = 528 bytes (16B-phase shift per row -> conflict-free ldmatrix)
#define RSTRIDE_B 528

// smem byte offsets
#define SM_WHI  0
#define SM_WLO  (SM_WHI + NCOLS * RSTRIDE_B)        // 67584
#define SM_XHI  (SM_WLO + NCOLS * RSTRIDE_B)        // 135168
#define SM_XLO  (SM_XHI + MT * RSTRIDE_B)           // 152064
#define SM_BIAS (SM_XLO + MT * RSTRIDE_B)           // 168960
#define SMEM_B  (SM_BIAS + NCOLS * 4)               // 169472

__device__ int g_list[NTASKS * LIST_STRIDE];
__device__ int g_cnt[NTASKS];

// ================= prep: bucket sample indices per task ====================
__global__ void build_lists(const int* __restrict__ ids, int B) {
    __shared__ int cnt;
    const int t = blockIdx.x;
    if (threadIdx.x == 0) cnt = 0;
    __syncthreads();
    for (int i = threadIdx.x; i < B; i += blockDim.x) {
        if (ids[i] == t) {
            int p = atomicAdd(&cnt, 1);
            g_list[t * LIST_STRIDE + p] = i;
        }
    }
    __syncthreads();
    if (threadIdx.x == 0) g_cnt[t] = cnt;
}

// ================= helpers =================================================
__device__ __forceinline__ uint32_t smem_u32(const void* p) {
    uint32_t a;
    asm("{ .reg .u64 t; cvta.to.shared.u64 t, %1; cvt.u32.u64 %0, t; }" : "=r"(a) : "l"(p));
    return a;
}
__device__ __forceinline__ uint32_t pack_bf16(float a, float b) {
    __nv_bfloat162 t = __floats2bfloat162_rn(a, b);
    return *(uint32_t*)&t;
}
__device__ __forceinline__ float bf_hi(float x) {
    return __bfloat162float(__float2bfloat16(x));
}

#define LDSM_X4(r0, r1, r2, r3, addr)                                      \
    asm volatile("ldmatrix.sync.aligned.m8n8.x4.shared.b16 {%0,%1,%2,%3}, [%4];" \
        : "=r"(r0), "=r"(r1), "=r"(r2), "=r"(r3) : "r"(addr))

#define MMA_BF16(c, a0, a1, a2, a3, b0, b1)                                \
    asm volatile("mma.sync.aligned.m16n8k16.row.col.f32.bf16.bf16.f32 "    \
        "{%0,%1,%2,%3}, {%4,%5,%6,%7}, {%8,%9}, {%0,%1,%2,%3};"            \
        : "+f"((c)[0]), "+f"((c)[1]), "+f"((c)[2]), "+f"((c)[3])           \
        : "r"(a0), "r"(a1), "r"(a2), "r"(a3), "r"(b0), "r"(b1))

// ================= main: CTA = (task, 128-col chunk) =======================
__global__ __launch_bounds__(THREADS, 1)
void affine_hmma_kernel(const float* __restrict__ inputs,
                        const float* __restrict__ te,
                        float* __restrict__ out) {
    extern __shared__ char smem[];
    const uint32_t sb = smem_u32(smem);
    float* bias_sm = (float*)(smem + SM_BIAS);

    const int task    = blockIdx.y;
    const int colBase = blockIdx.x * NCOLS;
    const int tid     = threadIdx.x;
    const int lane    = tid & 31;
    const int wid     = tid >> 5;

    const int n = g_cnt[task];
    if (n == 0) return;
    const int lbase = task * LIST_STRIDE;

    const float* emb = te + (size_t)task * FULL_EMBED;

    // ---- stage bias ----
    if (tid < NCOLS) bias_sm[tid] = emb[WSIZE + colBase + tid];

    // ---- stage W hi/lo: [c][k] bf16, row stride RSTRIDE_B ----
    {
        const int c  = tid & (NCOLS - 1);
        const int kh = (tid >> 7) * 128;
        const float4* wg = (const float4*)(emb + (size_t)(colBase + c) * IN_CH + kh);
        char* whi = smem + SM_WHI + c * RSTRIDE_B;
        char* wlo = smem + SM_WLO + c * RSTRIDE_B;
        #pragma unroll 8
        for (int kv = 0; kv < 32; kv++) {
            float4 v = wg[kv];
            int kb = (kh + kv * 4) * 2;   // byte offset
            float hx = bf_hi(v.x), hy = bf_hi(v.y), hz = bf_hi(v.z), hw = bf_hi(v.w);
            *(uint32_t*)(whi + kb)     = pack_bf16(v.x, v.y);
            *(uint32_t*)(whi + kb + 4) = pack_bf16(v.z, v.w);
            *(uint32_t*)(wlo + kb)     = pack_bf16(v.x - hx, v.y - hy);
            *(uint32_t*)(wlo + kb + 4) = pack_bf16(v.z - hz, v.w - hw);
        }
    }

    // ---- warp tiling: 2 (M) x 4 (N); warp = m16 x n32 ----
    const int warp_m = wid >> 2;          // 0..1
    const int warp_n = wid & 3;           // 0..3
    const int mrow0  = warp_m * 16;
    const int ncol0  = warp_n * 32;       // within the 128-col chunk
    const int g      = lane >> 2;         // group id 0..7
    const int tg     = lane & 3;          // 0..3

    // ldmatrix per-lane address offsets
    // A (x4): row = mrow0 + ((L>>3)&1)*8 + (L&7); kbyte += (L>>4)*16
    const int a_row  = mrow0 + ((lane >> 3) & 1) * 8 + (lane & 7);
    const uint32_t a_off = (uint32_t)a_row * RSTRIDE_B + ((lane >> 4) * 16);
    // B (x4, covers 2 n8 blocks): col = base + (L>>4)*8 + (L&7); kbyte += ((L>>3)&1)*16
    const int b_col0 = ncol0 + (lane >> 4) * 8 + (lane & 7);          // cblk 0
    const uint32_t b_koff = ((lane >> 3) & 1) * 16;
    const uint32_t bh0 = sb + SM_WHI + (uint32_t)b_col0 * RSTRIDE_B + b_koff;
    const uint32_t bh1 = bh0 + 16 * RSTRIDE_B;                        // cblk 1 (+16 cols)
    const uint32_t bl0 = bh0 + (SM_WLO - SM_WHI);
    const uint32_t bl1 = bh1 + (SM_WLO - SM_WHI);
    const uint32_t ahi = sb + SM_XHI + a_off;
    const uint32_t alo = sb + SM_XLO + a_off;

    // ---- loop over 32-row tiles ----
    for (int m0 = 0; m0 < n; m0 += MT) {
        __syncthreads();   // W stage (first iter) / previous k-loop reads done

        // stage X hi/lo: warp handles 4 rows, fully coalesced row loads
        {
            #pragma unroll
            for (int rr = 0; rr < 4; rr++) {
                const int r   = wid * 4 + rr;
                const int row = m0 + r;
                float4 v0, v1;
                if (row < n) {
                    const float4* xg =
                        (const float4*)(inputs + (size_t)g_list[lbase + row] * IN_CH);
                    v0 = xg[lane];
                    v1 = xg[lane + 32];
                } else {
                    v0 = make_float4(0.f, 0.f, 0.f, 0.f);
                    v1 = make_float4(0.f, 0.f, 0.f, 0.f);
                }
                char* xhi = smem + SM_XHI + r * RSTRIDE_B;
                char* xlo = smem + SM_XLO + r * RSTRIDE_B;
                const int kb0 = lane * 8;          // k = lane*4
                const int kb1 = 256 + lane * 8;    // k = 128 + lane*4
                float h;
                h = bf_hi(v0.x); float l0x = v0.x - h;
                h = bf_hi(v0.y); float l0y = v0.y - h;
                h = bf_hi(v0.z); float l0z = v0.z - h;
                h = bf_hi(v0.w); float l0w = v0.w - h;
                *(uint32_t*)(xhi + kb0)     = pack_bf16(v0.x, v0.y);
                *(uint32_t*)(xhi + kb0 + 4) = pack_bf16(v0.z, v0.w);
                *(uint32_t*)(xlo + kb0)     = pack_bf16(l0x, l0y);
                *(uint32_t*)(xlo + kb0 + 4) = pack_bf16(l0z, l0w);
                h = bf_hi(v1.x); float l1x = v1.x - h;
                h = bf_hi(v1.y); float l1y = v1.y - h;
                h = bf_hi(v1.z); float l1z = v1.z - h;
                h = bf_hi(v1.w); float l1w = v1.w - h;
                *(uint32_t*)(xhi + kb1)     = pack_bf16(v1.x, v1.y);
                *(uint32_t*)(xhi + kb1 + 4) = pack_bf16(v1.z, v1.w);
                *(uint32_t*)(xlo + kb1)     = pack_bf16(l1x, l1y);
                *(uint32_t*)(xlo + kb1 + 4) = pack_bf16(l1z, l1w);
            }
        }
        __syncthreads();

        float acc[4][4];
        #pragma unroll
        for (int f = 0; f < 4; f++)
            #pragma unroll
            for (int j = 0; j < 4; j++) acc[f][j] = 0.f;

        #pragma unroll 4
        for (int ks = 0; ks < IN_CH; ks += 16) {
            const uint32_t kb = ks * 2;
            uint32_t aH0, aH1, aH2, aH3, aL0, aL1, aL2, aL3;
            LDSM_X4(aH0, aH1, aH2, aH3, ahi + kb);
            LDSM_X4(aL0, aL1, aL2, aL3, alo + kb);
            // B: r0 = frag(n8 even) klo, r1 = frag even khi, r2/r3 = frag odd
            uint32_t h00, h01, h02, h03, h10, h11, h12, h13;
            uint32_t l00, l01, l02, l03, l10, l11, l12, l13;
            LDSM_X4(h00, h01, h02, h03, bh0 + kb);
            LDSM_X4(h10, h11, h12, h13, bh1 + kb);
            LDSM_X4(l00, l01, l02, l03, bl0 + kb);
            LDSM_X4(l10, l11, l12, l13, bl1 + kb);
            // hi * hi
            MMA_BF16(acc[0], aH0, aH1, aH2, aH3, h00, h01);
            MMA_BF16(acc[1], aH0, aH1, aH2, aH3, h02, h03);
            MMA_BF16(acc[2], aH0, aH1, aH2, aH3, h10, h11);
            MMA_BF16(acc[3], aH0, aH1, aH2, aH3, h12, h13);
            // hi * lo
            MMA_BF16(acc[0], aH0, aH1, aH2, aH3, l00, l01);
            MMA_BF16(acc[1], aH0, aH1, aH2, aH3, l02, l03);
            MMA_BF16(acc[2], aH0, aH1, aH2, aH3, l10, l11);
            MMA_BF16(acc[3], aH0, aH1, aH2, aH3, l12, l13);
            // lo * hi
            MMA_BF16(acc[0], aL0, aL1, aL2, aL3, h00, h01);
            MMA_BF16(acc[1], aL0, aL1, aL2, aL3, h02, h03);
            MMA_BF16(acc[2], aL0, aL1, aL2, aL3, h10, h11);
            MMA_BF16(acc[3], aL0, aL1, aL2, aL3, h12, h13);
        }

        // ---- epilogue ----
        // frag f covers cols ncol0 + (f&1)*8 + (f>>1)*16 : c0,c1 row g; c2,c3 row g+8
        const int row0 = m0 + mrow0 + g;
        const int row1 = row0 + 8;
        #pragma unroll
        for (int f = 0; f < 4; f++) {
            const int cloc = ncol0 + ((f & 1) ? 8 : 0) + ((f >> 1) ? 16 : 0) + tg * 2;
            const float b0 = bias_sm[cloc];
            const float b1 = bias_sm[cloc + 1];
            if (row0 < n) {
                float* p = out + (size_t)g_list[lbase + row0] * OUT_CH + colBase + cloc;
                *(float2*)p = make_float2(acc[f][0] + b0, acc[f][1] + b1);
            }
            if (row1 < n) {
                float* p = out + (size_t)g_list[lbase + row1] * OUT_CH + colBase + cloc;
                *(float2*)p = make_float2(acc[f][2] + b0, acc[f][3] + b1);
            }
        }
    }
}

// ================= launch ==================================================
extern "C" void kernel_launch(void* const* d_in, const int* in_sizes, int n_in,
                              void* d_out, int out_size) {
    const float* inputs   = (const float*)d_in[0];
    const int*   task_ids = (const int*)d_in[1];   // JAX x64 disabled -> int32
    const float* te       = (const float*)d_in[2];
    float*       out      = (float*)d_out;
    int B = in_sizes[1];

    build_lists<<<NTASKS, 256>>>(task_ids, B);

    cudaFuncSetAttribute(affine_hmma_kernel,
                         cudaFuncAttributeMaxDynamicSharedMemorySize, SMEM_B);
    dim3 grid(OUT_CH / NCOLS, NTASKS, 1);   // (2, 64) = 128 CTAs
    affine_hmma_kernel<<<grid, THREADS, SMEM_B>>>(inputs, te, out);
}

// round 8
// speedup vs baseline: 1.8151x; 1.0102x over previous
#include <cuda_runtime.h>
#include <cuda_bf16.h>
#include <cstdint>

#define IN_CH   256
#define OUT_CH  256
#define NTASKS  64
#define WSIZE   (OUT_CH * IN_CH)
#define FULL_EMBED (WSIZE + OUT_CH)
#define BMAX    4096
#define LIST_STRIDE 4096
#define NCOLS   64              // output cols per CTA
#define MT      32              // rows per M-tile
#define THREADS 128

// bf16 row stride: 264 elements = 528 bytes (16B-phase shift per row -> conflict-free ldmatrix)
#define RSTRIDE_B 528

// smem byte offsets
#define SM_WHI  0
#define SM_WLO  (SM_WHI + NCOLS * RSTRIDE_B)        // 33792
#define SM_XHI  (SM_WLO + NCOLS * RSTRIDE_B)        // 67584
#define SM_XLO  (SM_XHI + MT * RSTRIDE_B)           // 84480
#define SM_BIAS (SM_XLO + MT * RSTRIDE_B)           // 101376
#define SMEM_B  (SM_BIAS + NCOLS * 4)               // 101632 (~99.3KB -> 2 CTAs/SM)

__device__ int g_list[NTASKS * LIST_STRIDE];
__device__ int g_cnt[NTASKS];

// ================= prep: bucket sample indices per task ====================
__global__ void build_lists(const int* __restrict__ ids, int B) {
    __shared__ int cnt;
    const int t = blockIdx.x;
    if (threadIdx.x == 0) cnt = 0;
    __syncthreads();
    for (int i = threadIdx.x; i < B; i += blockDim.x) {
        if (ids[i] == t) {
            int p = atomicAdd(&cnt, 1);
            g_list[t * LIST_STRIDE + p] = i;
        }
    }
    __syncthreads();
    if (threadIdx.x == 0) g_cnt[t] = cnt;
}

// ================= helpers =================================================
__device__ __forceinline__ uint32_t smem_u32(const void* p) {
    uint32_t a;
    asm("{ .reg .u64 t; cvta.to.shared.u64 t, %1; cvt.u32.u64 %0, t; }" : "=r"(a) : "l"(p));
    return a;
}
__device__ __forceinline__ uint32_t pack_bf16(float a, float b) {
    __nv_bfloat162 t = __floats2bfloat162_rn(a, b);
    return *(uint32_t*)&t;
}
__device__ __forceinline__ float bf_hi(float x) {
    return __bfloat162float(__float2bfloat16(x));
}

#define LDSM_X4(r0, r1, r2, r3, addr)                                      \
    asm volatile("ldmatrix.sync.aligned.m8n8.x4.shared.b16 {%0,%1,%2,%3}, [%4];" \
        : "=r"(r0), "=r"(r1), "=r"(r2), "=r"(r3) : "r"(addr))

#define MMA_BF16(c, a0, a1, a2, a3, b0, b1)                                \
    asm volatile("mma.sync.aligned.m16n8k16.row.col.f32.bf16.bf16.f32 "    \
        "{%0,%1,%2,%3}, {%4,%5,%6,%7}, {%8,%9}, {%0,%1,%2,%3};"            \
        : "+f"((c)[0]), "+f"((c)[1]), "+f"((c)[2]), "+f"((c)[3])           \
        : "r"(a0), "r"(a1), "r"(a2), "r"(a3), "r"(b0), "r"(b1))

// ================= main: CTA = (task, 64-col chunk) ========================
__global__ __launch_bounds__(THREADS, 2)
void affine_hmma_kernel(const float* __restrict__ inputs,
                        const float* __restrict__ te,
                        float* __restrict__ out) {
    extern __shared__ char smem[];
    const uint32_t sb = smem_u32(smem);
    float* bias_sm = (float*)(smem + SM_BIAS);

    const int task    = blockIdx.y;
    const int colBase = blockIdx.x * NCOLS;
    const int tid     = threadIdx.x;
    const int lane    = tid & 31;
    const int wid     = tid >> 5;

    const int n = g_cnt[task];
    if (n == 0) return;
    const int lbase = task * LIST_STRIDE;

    const float* emb = te + (size_t)task * FULL_EMBED;

    // ---- stage bias ----
    if (tid < NCOLS) bias_sm[tid] = emb[WSIZE + colBase + tid];

    // ---- stage W hi/lo: [c][k] bf16, row stride RSTRIDE_B ----
    {
        const int c  = tid & (NCOLS - 1);
        const int kh = (tid >> 6) * 128;
        const float4* wg = (const float4*)(emb + (size_t)(colBase + c) * IN_CH + kh);
        char* whi = smem + SM_WHI + c * RSTRIDE_B;
        char* wlo = smem + SM_WLO + c * RSTRIDE_B;
        #pragma unroll 8
        for (int kv = 0; kv < 32; kv++) {
            float4 v = wg[kv];
            int kb = (kh + kv * 4) * 2;   // byte offset
            float hx = bf_hi(v.x), hy = bf_hi(v.y), hz = bf_hi(v.z), hw = bf_hi(v.w);
            *(uint32_t*)(whi + kb)     = pack_bf16(v.x, v.y);
            *(uint32_t*)(whi + kb + 4) = pack_bf16(v.z, v.w);
            *(uint32_t*)(wlo + kb)     = pack_bf16(v.x - hx, v.y - hy);
            *(uint32_t*)(wlo + kb + 4) = pack_bf16(v.z - hz, v.w - hw);
        }
    }

    // ---- warp tiling: 2 (M) x 2 (N); warp = m16 x n32 ----
    const int warp_m = wid >> 1;          // 0..1
    const int warp_n = wid & 1;           // 0..1
    const int mrow0  = warp_m * 16;
    const int ncol0  = warp_n * 32;       // within the 64-col chunk
    const int g      = lane >> 2;         // group id 0..7
    const int tg     = lane & 3;          // 0..3

    // ldmatrix per-lane address offsets (same mapping as verified R7)
    const int a_row  = mrow0 + ((lane >> 3) & 1) * 8 + (lane & 7);
    const uint32_t a_off = (uint32_t)a_row * RSTRIDE_B + ((lane >> 4) * 16);
    const int b_col0 = ncol0 + (lane >> 4) * 8 + (lane & 7);
    const uint32_t b_koff = ((lane >> 3) & 1) * 16;
    const uint32_t bh0 = sb + SM_WHI + (uint32_t)b_col0 * RSTRIDE_B + b_koff;
    const uint32_t bh1 = bh0 + 16 * RSTRIDE_B;
    const uint32_t bl0 = bh0 + (SM_WLO - SM_WHI);
    const uint32_t bl1 = bh1 + (SM_WLO - SM_WHI);
    const uint32_t ahi = sb + SM_XHI + a_off;
    const uint32_t alo = sb + SM_XLO + a_off;

    // ---- loop over 32-row tiles ----
    for (int m0 = 0; m0 < n; m0 += MT) {
        __syncthreads();   // W stage (first iter) / previous k-loop reads done

        // stage X hi/lo: each warp handles 8 rows, fully coalesced row loads
        {
            #pragma unroll
            for (int rr = 0; rr < 8; rr++) {
                const int r   = wid * 8 + rr;
                const int row = m0 + r;
                float4 v0, v1;
                if (row < n) {
                    const float4* xg =
                        (const float4*)(inputs + (size_t)g_list[lbase + row] * IN_CH);
                    v0 = xg[lane];
                    v1 = xg[lane + 32];
                } else {
                    v0 = make_float4(0.f, 0.f, 0.f, 0.f);
                    v1 = make_float4(0.f, 0.f, 0.f, 0.f);
                }
                char* xhi = smem + SM_XHI + r * RSTRIDE_B;
                char* xlo = smem + SM_XLO + r * RSTRIDE_B;
                const int kb0 = lane * 8;          // k = lane*4
                const int kb1 = 256 + lane * 8;    // k = 128 + lane*4
                float h;
                h = bf_hi(v0.x); float l0x = v0.x - h;
                h = bf_hi(v0.y); float l0y = v0.y - h;
                h = bf_hi(v0.z); float l0z = v0.z - h;
                h = bf_hi(v0.w); float l0w = v0.w - h;
                *(uint32_t*)(xhi + kb0)     = pack_bf16(v0.x, v0.y);
                *(uint32_t*)(xhi + kb0 + 4) = pack_bf16(v0.z, v0.w);
                *(uint32_t*)(xlo + kb0)     = pack_bf16(l0x, l0y);
                *(uint32_t*)(xlo + kb0 + 4) = pack_bf16(l0z, l0w);
                h = bf_hi(v1.x); float l1x = v1.x - h;
                h = bf_hi(v1.y); float l1y = v1.y - h;
                h = bf_hi(v1.z); float l1z = v1.z - h;
                h = bf_hi(v1.w); float l1w = v1.w - h;
                *(uint32_t*)(xhi + kb1)     = pack_bf16(v1.x, v1.y);
                *(uint32_t*)(xhi + kb1 + 4) = pack_bf16(v1.z, v1.w);
                *(uint32_t*)(xlo + kb1)     = pack_bf16(l1x, l1y);
                *(uint32_t*)(xlo + kb1 + 4) = pack_bf16(l1z, l1w);
            }
        }
        __syncthreads();

        float acc[4][4];
        #pragma unroll
        for (int f = 0; f < 4; f++)
            #pragma unroll
            for (int j = 0; j < 4; j++) acc[f][j] = 0.f;

        #pragma unroll 4
        for (int ks = 0; ks < IN_CH; ks += 16) {
            const uint32_t kb = ks * 2;
            uint32_t aH0, aH1, aH2, aH3, aL0, aL1, aL2, aL3;
            LDSM_X4(aH0, aH1, aH2, aH3, ahi + kb);
            LDSM_X4(aL0, aL1, aL2, aL3, alo + kb);
            uint32_t h00, h01, h02, h03, h10, h11, h12, h13;
            uint32_t l00, l01, l02, l03, l10, l11, l12, l13;
            LDSM_X4(h00, h01, h02, h03, bh0 + kb);
            LDSM_X4(h10, h11, h12, h13, bh1 + kb);
            LDSM_X4(l00, l01, l02, l03, bl0 + kb);
            LDSM_X4(l10, l11, l12, l13, bl1 + kb);
            // hi * hi
            MMA_BF16(acc[0], aH0, aH1, aH2, aH3, h00, h01);
            MMA_BF16(acc[1], aH0, aH1, aH2, aH3, h02, h03);
            MMA_BF16(acc[2], aH0, aH1, aH2, aH3, h10, h11);
            MMA_BF16(acc[3], aH0, aH1, aH2, aH3, h12, h13);
            // hi * lo
            MMA_BF16(acc[0], aH0, aH1, aH2, aH3, l00, l01);
            MMA_BF16(acc[1], aH0, aH1, aH2, aH3, l02, l03);
            MMA_BF16(acc[2], aH0, aH1, aH2, aH3, l10, l11);
            MMA_BF16(acc[3], aH0, aH1, aH2, aH3, l12, l13);
            // lo * hi
            MMA_BF16(acc[0], aL0, aL1, aL2, aL3, h00, h01);
            MMA_BF16(acc[1], aL0, aL1, aL2, aL3, h02, h03);
            MMA_BF16(acc[2], aL0, aL1, aL2, aL3, h10, h11);
            MMA_BF16(acc[3], aL0, aL1, aL2, aL3, h12, h13);
        }

        // ---- epilogue ----
        const int row0 = m0 + mrow0 + g;
        const int row1 = row0 + 8;
        #pragma unroll
        for (int f = 0; f < 4; f++) {
            const int cloc = ncol0 + ((f & 1) ? 8 : 0) + ((f >> 1) ? 16 : 0) + tg * 2;
            const float b0 = bias_sm[cloc];
            const float b1 = bias_sm[cloc + 1];
            if (row0 < n) {
                float* p = out + (size_t)g_list[lbase + row0] * OUT_CH + colBase + cloc;
                *(float2*)p = make_float2(acc[f][0] + b0, acc[f][1] + b1);
            }
            if (row1 < n) {
                float* p = out + (size_t)g_list[lbase + row1] * OUT_CH + colBase + cloc;
                *(float2*)p = make_float2(acc[f][2] + b0, acc[f][3] + b1);
            }
        }
    }
}

// ================= launch ==================================================
extern "C" void kernel_launch(void* const* d_in, const int* in_sizes, int n_in,
                              void* d_out, int out_size) {
    const float* inputs   = (const float*)d_in[0];
    const int*   task_ids = (const int*)d_in[1];   // JAX x64 disabled -> int32
    const float* te       = (const float*)d_in[2];
    float*       out      = (float*)d_out;
    int B = in_sizes[1];

    build_lists<<<NTASKS, 256>>>(task_ids, B);

    cudaFuncSetAttribute(affine_hmma_kernel,
                         cudaFuncAttributeMaxDynamicSharedMemorySize, SMEM_B);
    dim3 grid(OUT_CH / NCOLS, NTASKS, 1);   // (4, 64) = 256 CTAs, 2/SM
    affine_hmma_kernel<<<grid, THREADS, SMEM_B>>>(inputs, te, out);
}